// round 7
// baseline (speedup 1.0000x reference)
#include <cuda_runtime.h>
#include <cuda_bf16.h>
#include <cstdint>

// Problem constants
#define EDIM 1024
#define BATCH 2
#define SEQ 2048
#define NHEADS 16
#define HDIM 64
#define MROWS (BATCH * SEQ)          // 4096
#define QSCALE 0.125f                // 1/sqrt(64), exact power of two

// ---------------------------------------------------------------------------
// Scratch (allocation-free: static __device__ globals)
// ---------------------------------------------------------------------------
__device__ __nv_bfloat16 g_qsh[MROWS * EDIM], g_qsl[MROWS * EDIM];
__device__ __nv_bfloat16 g_ksh[MROWS * EDIM], g_ksl[MROWS * EDIM];
__device__ __nv_bfloat16 g_vsh[MROWS * EDIM], g_vsl[MROWS * EDIM];
__device__ __nv_bfloat16 g_wqh[EDIM * EDIM], g_wql[EDIM * EDIM];
__device__ __nv_bfloat16 g_wkh[EDIM * EDIM], g_wkl[EDIM * EDIM];
__device__ __nv_bfloat16 g_wvh[EDIM * EDIM], g_wvl[EDIM * EDIM];
__device__ __nv_bfloat16 g_woh[EDIM * EDIM], g_wol[EDIM * EDIM];
__device__ __nv_bfloat16 g_Qhi[MROWS * EDIM], g_Qlo[MROWS * EDIM];
__device__ __nv_bfloat16 g_Khi[MROWS * EDIM], g_Klo[MROWS * EDIM];
__device__ __nv_bfloat16 g_Vhi[MROWS * EDIM], g_Vlo[MROWS * EDIM];
__device__ __nv_bfloat16 g_Ohi[MROWS * EDIM], g_Olo[MROWS * EDIM];

// ---------------------------------------------------------------------------
// Primitives
// ---------------------------------------------------------------------------
__device__ __forceinline__ uint32_t smem_u32(const void* p) {
    uint32_t a;
    asm("{ .reg .u64 t; cvta.to.shared.u64 t, %1; cvt.u32.u64 %0, t; }"
        : "=r"(a) : "l"(p));
    return a;
}

#define LDSM_X4(r0, r1, r2, r3, addr) \
    asm volatile("ldmatrix.sync.aligned.m8n8.x4.shared.b16 {%0,%1,%2,%3}, [%4];" \
        : "=r"(r0), "=r"(r1), "=r"(r2), "=r"(r3) : "r"(addr))

#define LDSM_X4T(r0, r1, r2, r3, addr) \
    asm volatile("ldmatrix.sync.aligned.m8n8.x4.trans.shared.b16 {%0,%1,%2,%3}, [%4];" \
        : "=r"(r0), "=r"(r1), "=r"(r2), "=r"(r3) : "r"(addr))

#define CP_ASYNC16(saddr, gptr) \
    asm volatile("cp.async.cg.shared.global [%0], [%1], 16;" \
        :: "r"(saddr), "l"(gptr))

#define CP_COMMIT() asm volatile("cp.async.commit_group;" ::: "memory")
#define CP_WAIT1()  asm volatile("cp.async.wait_group 1;" ::: "memory")
#define CP_WAIT0()  asm volatile("cp.async.wait_group 0;" ::: "memory")

__device__ __forceinline__ void mma_bf16(float* c, uint32_t a0, uint32_t a1,
                                         uint32_t a2, uint32_t a3,
                                         uint32_t b0, uint32_t b1) {
    asm volatile(
        "mma.sync.aligned.m16n8k16.row.col.f32.bf16.bf16.f32 "
        "{%0,%1,%2,%3}, {%4,%5,%6,%7}, {%8,%9}, {%0,%1,%2,%3};"
        : "+f"(c[0]), "+f"(c[1]), "+f"(c[2]), "+f"(c[3])
        : "r"(a0), "r"(a1), "r"(a2), "r"(a3), "r"(b0), "r"(b1));
}

__device__ __forceinline__ uint32_t pack_bf16(float x, float y) {
    __nv_bfloat162 t = __floats2bfloat162_rn(x, y);
    return *(uint32_t*)&t;
}

__device__ __forceinline__ void split_pack2(float x, float y,
                                            uint32_t& hi, uint32_t& lo) {
    __nv_bfloat16 hx = __float2bfloat16(x);
    __nv_bfloat16 hy = __float2bfloat16(y);
    __nv_bfloat162 h2 = __halves2bfloat162(hx, hy);
    hi = *(uint32_t*)&h2;
    lo = pack_bf16(x - __bfloat162float(hx), y - __bfloat162float(hy));
}

// ---------------------------------------------------------------------------
// Splits
// ---------------------------------------------------------------------------
__device__ __forceinline__ void split_body(
    const float* __restrict__ x, __nv_bfloat16* __restrict__ hi,
    __nv_bfloat16* __restrict__ lo, int n, int bx)
{
    int i = (bx * 256 + threadIdx.x) * 4;
    if (i >= n) return;
    float4 v = *(const float4*)(x + i);
    uint32_t h01, l01, h23, l23;
    split_pack2(v.x, v.y, h01, l01);
    split_pack2(v.z, v.w, h23, l23);
    *(uint2*)(hi + i) = make_uint2(h01, h23);
    *(uint2*)(lo + i) = make_uint2(l01, l23);
}

__global__ __launch_bounds__(256) void split_all_kernel(
    const float* q, const float* k, const float* v,
    const float* wq, const float* wk, const float* wv, const float* wo)
{
    const int nA = MROWS * EDIM, nW = EDIM * EDIM;
    switch (blockIdx.y) {
        case 0: split_body(q,  g_qsh, g_qsl, nA, blockIdx.x); break;
        case 1: split_body(k,  g_ksh, g_ksl, nA, blockIdx.x); break;
        case 2: split_body(v,  g_vsh, g_vsl, nA, blockIdx.x); break;
        case 3: split_body(wq, g_wqh, g_wql, nW, blockIdx.x); break;
        case 4: split_body(wk, g_wkh, g_wkl, nW, blockIdx.x); break;
        case 5: split_body(wv, g_wvh, g_wvl, nW, blockIdx.x); break;
        case 6: split_body(wo, g_woh, g_wol, nW, blockIdx.x); break;
    }
}

// ---------------------------------------------------------------------------
// HMMA bf16x3 GEMM body: C[128,256 tile] = Ahi Whi^T + Alo Whi^T + Ahi Wlo^T
// CTA 128x256, BK=32, 2-stage cp.async, 8 warps each 64x64 (mt=4, nt=8).
// Wavefront ratio: 16 LDSM.X4 per 96 mma = 0.67 wf/mma.
// ---------------------------------------------------------------------------
#define GPAD 40
#define GT_A (128 * GPAD * 2)            // 10240
#define GT_B (256 * GPAD * 2)            // 20480
#define GSTAGE (2 * GT_A + 2 * GT_B)     // 61440
#define GSMEM_BYTES (2 * GSTAGE)         // 122880

template <bool F32OUT>
__device__ __forceinline__ void gemm_body(
    const __nv_bfloat16* __restrict__ Ahi, const __nv_bfloat16* __restrict__ Alo,
    const __nv_bfloat16* __restrict__ Whi, const __nv_bfloat16* __restrict__ Wlo,
    float* __restrict__ Cf,
    __nv_bfloat16* __restrict__ Chi, __nv_bfloat16* __restrict__ Clo,
    float scale)
{
    extern __shared__ __nv_bfloat16 hsm[];
    const uint32_t sb = smem_u32(hsm);

    const int tid = threadIdx.x;
    const int wid = tid >> 5;
    const int lane = tid & 31;
    const int bm = blockIdx.y * 128;
    const int bn = blockIdx.x * 256;
    const int moff = (wid >> 2) * 64;   // 0 or 64
    const int noff = (wid & 3) * 64;    // 0..192

    float acc[4][8][4];
#pragma unroll
    for (int mt = 0; mt < 4; mt++)
#pragma unroll
        for (int nt = 0; nt < 8; nt++)
#pragma unroll
            for (int r = 0; r < 4; r++) acc[mt][nt][r] = 0.f;

    const uint32_t a_off = ((moff + (lane & 15)) * GPAD + (lane >> 4) * 8) * 2;
    const uint32_t b4_base =
        ((noff + ((lane >> 4) & 1) * 8 + (lane & 7)) * GPAD + ((lane >> 3) & 1) * 8) * 2;

    auto load_stage = [&](int t) {
        const uint32_t s0 = sb + (t & 1) * GSTAGE;
        const int k0 = t * 32;
        // A: 1024 chunks of 16B (2 tiles x 128 rows x 4 chunks) -> 4/thread
#pragma unroll
        for (int i = 0; i < 4; i++) {
            int l = i * 256 + tid;
            int tile = l >> 9;
            int r = (l >> 2) & 127;
            int c = (l & 3) * 8;
            const __nv_bfloat16* g = (tile ? Alo : Ahi) + (size_t)(bm + r) * EDIM + k0 + c;
            CP_ASYNC16(s0 + tile * GT_A + (uint32_t)(r * GPAD + c) * 2, g);
        }
        // B: 2048 chunks (2 tiles x 256 rows x 4 chunks) -> 8/thread
#pragma unroll
        for (int i = 0; i < 8; i++) {
            int l = i * 256 + tid;
            int tile = l >> 10;
            int r = (l >> 2) & 255;
            int c = (l & 3) * 8;
            const __nv_bfloat16* g = (tile ? Wlo : Whi) + (size_t)(bn + r) * EDIM + k0 + c;
            CP_ASYNC16(s0 + 2 * GT_A + tile * GT_B + (uint32_t)(r * GPAD + c) * 2, g);
        }
    };

    const int NT = EDIM / 32;   // 32
    load_stage(0);
    CP_COMMIT();

    for (int t = 0; t < NT; t++) {
        if (t + 1 < NT) {
            load_stage(t + 1);
            CP_COMMIT();
            CP_WAIT1();
        } else {
            CP_WAIT0();
        }
        __syncthreads();

        const uint32_t s0 = sb + (t & 1) * GSTAGE;
        const uint32_t aHiB = s0;
        const uint32_t aLoB = s0 + GT_A;
        const uint32_t wHiB = s0 + 2 * GT_A;
        const uint32_t wLoB = s0 + 2 * GT_A + GT_B;

#pragma unroll
        for (int ks = 0; ks < 2; ks++) {
            const uint32_t koff = ks * 32;
            uint32_t ah[4][4], al[4][4];
#pragma unroll
            for (int mt = 0; mt < 4; mt++) {
                LDSM_X4(ah[mt][0], ah[mt][1], ah[mt][2], ah[mt][3],
                        aHiB + a_off + mt * (16 * GPAD * 2) + koff);
                LDSM_X4(al[mt][0], al[mt][1], al[mt][2], al[mt][3],
                        aLoB + a_off + mt * (16 * GPAD * 2) + koff);
            }
#pragma unroll
            for (int ntp = 0; ntp < 4; ntp++) {
                const uint32_t boff = b4_base + ntp * (16 * GPAD * 2) + koff;
                uint32_t b0, b1, b2, b3;
                LDSM_X4(b0, b1, b2, b3, wHiB + boff);
#pragma unroll
                for (int mt = 0; mt < 4; mt++) {
                    mma_bf16(acc[mt][2 * ntp],     ah[mt][0], ah[mt][1], ah[mt][2], ah[mt][3], b0, b1);
                    mma_bf16(acc[mt][2 * ntp + 1], ah[mt][0], ah[mt][1], ah[mt][2], ah[mt][3], b2, b3);
                }
#pragma unroll
                for (int mt = 0; mt < 4; mt++) {
                    mma_bf16(acc[mt][2 * ntp],     al[mt][0], al[mt][1], al[mt][2], al[mt][3], b0, b1);
                    mma_bf16(acc[mt][2 * ntp + 1], al[mt][0], al[mt][1], al[mt][2], al[mt][3], b2, b3);
                }
                uint32_t e0, e1, e2, e3;
                LDSM_X4(e0, e1, e2, e3, wLoB + boff);
#pragma unroll
                for (int mt = 0; mt < 4; mt++) {
                    mma_bf16(acc[mt][2 * ntp],     ah[mt][0], ah[mt][1], ah[mt][2], ah[mt][3], e0, e1);
                    mma_bf16(acc[mt][2 * ntp + 1], ah[mt][0], ah[mt][1], ah[mt][2], ah[mt][3], e2, e3);
                }
            }
        }
        __syncthreads();
    }

    // Epilogue
#pragma unroll
    for (int mt = 0; mt < 4; mt++) {
#pragma unroll
        for (int nt = 0; nt < 8; nt++) {
            int r0 = bm + moff + mt * 16 + (lane >> 2);
            int c0 = bn + noff + nt * 8 + (lane & 3) * 2;
            if (F32OUT) {
                *(float2*)(Cf + (size_t)r0 * EDIM + c0) = make_float2(acc[mt][nt][0], acc[mt][nt][1]);
                *(float2*)(Cf + (size_t)(r0 + 8) * EDIM + c0) = make_float2(acc[mt][nt][2], acc[mt][nt][3]);
            } else {
                uint32_t h, l;
                split_pack2(acc[mt][nt][0] * scale, acc[mt][nt][1] * scale, h, l);
                *(uint32_t*)(Chi + (size_t)r0 * EDIM + c0) = h;
                *(uint32_t*)(Clo + (size_t)r0 * EDIM + c0) = l;
                split_pack2(acc[mt][nt][2] * scale, acc[mt][nt][3] * scale, h, l);
                *(uint32_t*)(Chi + (size_t)(r0 + 8) * EDIM + c0) = h;
                *(uint32_t*)(Clo + (size_t)(r0 + 8) * EDIM + c0) = l;
            }
        }
    }
}

// Merged QKV projections: blockIdx.z selects tensor.
__global__ __launch_bounds__(256) void hgemm_qkv()
{
    switch (blockIdx.z) {
        case 0: gemm_body<false>(g_qsh, g_qsl, g_wqh, g_wql, nullptr, g_Qhi, g_Qlo, QSCALE); break;
        case 1: gemm_body<false>(g_ksh, g_ksl, g_wkh, g_wkl, nullptr, g_Khi, g_Klo, 1.0f); break;
        case 2: gemm_body<false>(g_vsh, g_vsl, g_wvh, g_wvl, nullptr, g_Vhi, g_Vlo, 1.0f); break;
    }
}

// Output projection: fp32 out.
__global__ __launch_bounds__(256) void hgemm_out(float* __restrict__ out)
{
    gemm_body<true>(g_Ohi, g_Olo, g_woh, g_wol, out, nullptr, nullptr, 1.0f);
}

// ---------------------------------------------------------------------------
// Flash attention on HMMA, 3-stage cp.async KV ring, one sync per iteration.
// Epilogue writes pre-split Ohi/Olo directly.
// ---------------------------------------------------------------------------
#define FPAD 72
#define FQ_BYTES (128 * FPAD * 2)
#define FKV_BYTES (64 * FPAD * 2)
#define FSMEM_BYTES (2 * FQ_BYTES + 3 * 4 * FKV_BYTES)   // 147456

__global__ __launch_bounds__(256) void flash_hmma()
{
    extern __shared__ __nv_bfloat16 fsm[];
    const uint32_t sb = smem_u32(fsm);
    const uint32_t qHiB = sb;
    const uint32_t qLoB = sb + FQ_BYTES;
    const uint32_t kvB = sb + 2 * FQ_BYTES;

    const int tid = threadIdx.x;
    const int wid = tid >> 5;
    const int lane = tid & 31;
    const int qb = blockIdx.x * 128;
    const int h = blockIdx.y;
    const int b = blockIdx.z;

    const size_t qbase = ((size_t)b * SEQ + qb) * EDIM + h * HDIM;
    const size_t kvbase = (size_t)b * SEQ * EDIM + h * HDIM;

#pragma unroll
    for (int it = 0; it < 4; it++) {
        int l = it * 256 + tid;
        int r = l >> 3;
        int c = (l & 7) * 8;
        *(uint4*)(fsm + r * FPAD + c) = *(const uint4*)(g_Qhi + qbase + (size_t)r * EDIM + c);
        *(uint4*)(fsm + 128 * FPAD + r * FPAD + c) = *(const uint4*)(g_Qlo + qbase + (size_t)r * EDIM + c);
    }

    const int lr = tid >> 3;
    const int lc = (tid & 7) * 8;
    const size_t gKV0 = kvbase + (size_t)lr * EDIM + lc;
    const uint32_t sKV0 = (uint32_t)(lr * FPAD + lc) * 2;
    const uint32_t sKV1 = (uint32_t)((lr + 32) * FPAD + lc) * 2;

    auto load_stage = [&](int t) {
        const uint32_t s0 = kvB + (t % 3) * 4 * FKV_BYTES;
        const size_t g0 = gKV0 + (size_t)t * 64 * EDIM;
        CP_ASYNC16(s0 + 0 * FKV_BYTES + sKV0, g_Khi + g0);
        CP_ASYNC16(s0 + 0 * FKV_BYTES + sKV1, g_Khi + g0 + (size_t)32 * EDIM);
        CP_ASYNC16(s0 + 1 * FKV_BYTES + sKV0, g_Klo + g0);
        CP_ASYNC16(s0 + 1 * FKV_BYTES + sKV1, g_Klo + g0 + (size_t)32 * EDIM);
        CP_ASYNC16(s0 + 2 * FKV_BYTES + sKV0, g_Vhi + g0);
        CP_ASYNC16(s0 + 2 * FKV_BYTES + sKV1, g_Vhi + g0 + (size_t)32 * EDIM);
        CP_ASYNC16(s0 + 3 * FKV_BYTES + sKV0, g_Vlo + g0);
        CP_ASYNC16(s0 + 3 * FKV_BYTES + sKV1, g_Vlo + g0 + (size_t)32 * EDIM);
    };

    load_stage(0);
    CP_COMMIT();
    load_stage(1);
    CP_COMMIT();
    __syncthreads();

    const uint32_t a_off = ((wid * 16 + (lane & 15)) * FPAD + (lane >> 4) * 8) * 2;
    uint32_t qh[4][4], ql[4][4];
#pragma unroll
    for (int ks = 0; ks < 4; ks++) {
        LDSM_X4(qh[ks][0], qh[ks][1], qh[ks][2], qh[ks][3], qHiB + a_off + ks * 32);
        LDSM_X4(ql[ks][0], ql[ks][1], ql[ks][2], ql[ks][3], qLoB + a_off + ks * 32);
    }

    const uint32_t k4_off =
        ((((lane >> 4) & 1) * 8 + (lane & 7)) * FPAD + ((lane >> 3) & 1) * 8) * 2;
    const uint32_t v4_off =
        (((lane & 7) + ((lane >> 3) & 1) * 8) * FPAD + ((lane >> 4) & 1) * 8) * 2;

    float o[8][4];
#pragma unroll
    for (int nt = 0; nt < 8; nt++)
#pragma unroll
        for (int r = 0; r < 4; r++) o[nt][r] = 0.f;
    float m0 = -1e30f, m1 = -1e30f, l0 = 0.f, l1 = 0.f;

    const int NT = SEQ / 64;   // 32

    for (int t = 0; t < NT; t++) {
        if (t + 1 < NT) CP_WAIT1(); else CP_WAIT0();
        __syncthreads();

        const uint32_t s0 = kvB + (t % 3) * 4 * FKV_BYTES;
        const uint32_t kHiB = s0;
        const uint32_t kLoB = s0 + FKV_BYTES;
        const uint32_t vHiB = s0 + 2 * FKV_BYTES;
        const uint32_t vLoB = s0 + 3 * FKV_BYTES;

        float s[8][4];
#pragma unroll
        for (int nt = 0; nt < 8; nt++)
#pragma unroll
            for (int r = 0; r < 4; r++) s[nt][r] = 0.f;

#pragma unroll
        for (int ks = 0; ks < 4; ks++) {
            const uint32_t koff = ks * 32;
#pragma unroll
            for (int ntp = 0; ntp < 4; ntp++) {
                const uint32_t boff = k4_off + ntp * (16 * FPAD * 2) + koff;
                uint32_t h0, h1, h2, h3;
                LDSM_X4(h0, h1, h2, h3, kHiB + boff);
                mma_bf16(s[2 * ntp],     qh[ks][0], qh[ks][1], qh[ks][2], qh[ks][3], h0, h1);
                mma_bf16(s[2 * ntp + 1], qh[ks][0], qh[ks][1], qh[ks][2], qh[ks][3], h2, h3);
                mma_bf16(s[2 * ntp],     ql[ks][0], ql[ks][1], ql[ks][2], ql[ks][3], h0, h1);
                mma_bf16(s[2 * ntp + 1], ql[ks][0], ql[ks][1], ql[ks][2], ql[ks][3], h2, h3);
                uint32_t e0, e1, e2, e3;
                LDSM_X4(e0, e1, e2, e3, kLoB + boff);
                mma_bf16(s[2 * ntp],     qh[ks][0], qh[ks][1], qh[ks][2], qh[ks][3], e0, e1);
                mma_bf16(s[2 * ntp + 1], qh[ks][0], qh[ks][1], qh[ks][2], qh[ks][3], e2, e3);
            }
        }

        float mx0 = -1e30f, mx1 = -1e30f;
#pragma unroll
        for (int nt = 0; nt < 8; nt++) {
            mx0 = fmaxf(mx0, fmaxf(s[nt][0], s[nt][1]));
            mx1 = fmaxf(mx1, fmaxf(s[nt][2], s[nt][3]));
        }
        mx0 = fmaxf(mx0, __shfl_xor_sync(0xffffffffu, mx0, 1));
        mx0 = fmaxf(mx0, __shfl_xor_sync(0xffffffffu, mx0, 2));
        mx1 = fmaxf(mx1, __shfl_xor_sync(0xffffffffu, mx1, 1));
        mx1 = fmaxf(mx1, __shfl_xor_sync(0xffffffffu, mx1, 2));

        float mn0 = fmaxf(m0, mx0), mn1 = fmaxf(m1, mx1);
        float al0 = __expf(m0 - mn0), al1 = __expf(m1 - mn1);
        m0 = mn0; m1 = mn1;

        float sum0 = 0.f, sum1 = 0.f;
#pragma unroll
        for (int nt = 0; nt < 8; nt++) {
            s[nt][0] = __expf(s[nt][0] - mn0);
            s[nt][1] = __expf(s[nt][1] - mn0);
            s[nt][2] = __expf(s[nt][2] - mn1);
            s[nt][3] = __expf(s[nt][3] - mn1);
            sum0 += s[nt][0] + s[nt][1];
            sum1 += s[nt][2] + s[nt][3];
        }
        sum0 += __shfl_xor_sync(0xffffffffu, sum0, 1);
        sum0 += __shfl_xor_sync(0xffffffffu, sum0, 2);
        sum1 += __shfl_xor_sync(0xffffffffu, sum1, 1);
        sum1 += __shfl_xor_sync(0xffffffffu, sum1, 2);
        l0 = l0 * al0 + sum0;
        l1 = l1 * al1 + sum1;

#pragma unroll
        for (int nt = 0; nt < 8; nt++) {
            o[nt][0] *= al0; o[nt][1] *= al0;
            o[nt][2] *= al1; o[nt][3] *= al1;
        }

#pragma unroll
        for (int kt = 0; kt < 4; kt++) {
            uint32_t ph[4], pl[4];
            split_pack2(s[2 * kt][0],     s[2 * kt][1],     ph[0], pl[0]);
            split_pack2(s[2 * kt][2],     s[2 * kt][3],     ph[1], pl[1]);
            split_pack2(s[2 * kt + 1][0], s[2 * kt + 1][1], ph[2], pl[2]);
            split_pack2(s[2 * kt + 1][2], s[2 * kt + 1][3], ph[3], pl[3]);
#pragma unroll
            for (int ntp = 0; ntp < 4; ntp++) {
                const uint32_t voff = v4_off + kt * (16 * FPAD * 2) + ntp * 32;
                uint32_t vh0, vh1, vh2, vh3;
                LDSM_X4T(vh0, vh1, vh2, vh3, vHiB + voff);
                mma_bf16(o[2 * ntp],     ph[0], ph[1], ph[2], ph[3], vh0, vh1);
                mma_bf16(o[2 * ntp + 1], ph[0], ph[1], ph[2], ph[3], vh2, vh3);
                mma_bf16(o[2 * ntp],     pl[0], pl[1], pl[2], pl[3], vh0, vh1);
                mma_bf16(o[2 * ntp + 1], pl[0], pl[1], pl[2], pl[3], vh2, vh3);
                uint32_t vl0, vl1, vl2, vl3;
                LDSM_X4T(vl0, vl1, vl2, vl3, vLoB + voff);
                mma_bf16(o[2 * ntp],     ph[0], ph[1], ph[2], ph[3], vl0, vl1);
                mma_bf16(o[2 * ntp + 1], ph[0], ph[1], ph[2], ph[3], vl2, vl3);
            }
        }

        if (t + 2 < NT) {
            load_stage(t + 2);
            CP_COMMIT();
        }
    }

    // Epilogue: normalize, split, store pre-split bf16 hi/lo directly
    const int r0 = qb + wid * 16 + (lane >> 2);
    float inv0 = 1.f / l0, inv1 = 1.f / l1;
    const size_t obase = ((size_t)b * SEQ + r0) * EDIM + h * HDIM;
#pragma unroll
    for (int nt = 0; nt < 8; nt++) {
        int c = nt * 8 + (lane & 3) * 2;
        uint32_t hh, ll;
        split_pack2(o[nt][0] * inv0, o[nt][1] * inv0, hh, ll);
        *(uint32_t*)(g_Ohi + obase + c) = hh;
        *(uint32_t*)(g_Olo + obase + c) = ll;
        split_pack2(o[nt][2] * inv1, o[nt][3] * inv1, hh, ll);
        *(uint32_t*)(g_Ohi + obase + (size_t)8 * EDIM + c) = hh;
        *(uint32_t*)(g_Olo + obase + (size_t)8 * EDIM + c) = ll;
    }
}

// ---------------------------------------------------------------------------
// Launch: 4 kernels total
// ---------------------------------------------------------------------------
extern "C" void kernel_launch(void* const* d_in, const int* in_sizes, int n_in,
                              void* d_out, int out_size)
{
    (void)in_sizes; (void)n_in; (void)out_size;
    const float* q  = (const float*)d_in[0];
    const float* k  = (const float*)d_in[1];
    const float* v  = (const float*)d_in[2];
    const float* Wq = (const float*)d_in[3];
    const float* Wk = (const float*)d_in[4];
    const float* Wv = (const float*)d_in[5];
    const float* Wo = (const float*)d_in[6];
    float* out = (float*)d_out;

    static int attr_set = 0;
    if (!attr_set) {
        cudaFuncSetAttribute(hgemm_qkv,
                             cudaFuncAttributeMaxDynamicSharedMemorySize, GSMEM_BYTES);
        cudaFuncSetAttribute(hgemm_out,
                             cudaFuncAttributeMaxDynamicSharedMemorySize, GSMEM_BYTES);
        cudaFuncSetAttribute(flash_hmma,
                             cudaFuncAttributeMaxDynamicSharedMemorySize, FSMEM_BYTES);
        attr_set = 1;
    }

    const int nA = MROWS * EDIM;

    // 1) Split all 7 inputs
    dim3 sgrid(nA / 1024, 7);
    split_all_kernel<<<sgrid, 256>>>(q, k, v, Wq, Wk, Wv, Wo);

    // 2) Merged QKV projections: grid (N/256, M/128, 3) = (4, 32, 3)
    dim3 qkvgrid(EDIM / 256, MROWS / 128, 3);
    hgemm_qkv<<<qkvgrid, 256, GSMEM_BYTES>>>();

    // 3) Flash attention (epilogue emits pre-split O)
    dim3 fgrid(SEQ / 128, NHEADS, BATCH);
    flash_hmma<<<fgrid, 256, FSMEM_BYTES>>>();

    // 4) Output projection
    dim3 ogrid(EDIM / 256, MROWS / 128);
    hgemm_out<<<ogrid, 256, GSMEM_BYTES>>>(out);
}

// round 8
// speedup vs baseline: 1.5035x; 1.5035x over previous
#include <cuda_runtime.h>
#include <cuda_fp16.h>
#include <cstdint>

// Problem constants
#define EDIM 1024
#define BATCH 2
#define SEQ 2048
#define NHEADS 16
#define HDIM 64
#define MROWS (BATCH * SEQ)          // 4096
#define QSCALE 0.125f                // 1/sqrt(64), exact power of two

// ---------------------------------------------------------------------------
// Scratch (allocation-free). fp16x2 scheme: only A-side operands need lo.
// ---------------------------------------------------------------------------
__device__ __half g_qsh[MROWS * EDIM], g_qsl[MROWS * EDIM];
__device__ __half g_ksh[MROWS * EDIM], g_ksl[MROWS * EDIM];
__device__ __half g_vsh[MROWS * EDIM], g_vsl[MROWS * EDIM];
__device__ __half g_wqh[EDIM * EDIM];
__device__ __half g_wkh[EDIM * EDIM];
__device__ __half g_wvh[EDIM * EDIM];
__device__ __half g_woh[EDIM * EDIM];
__device__ __half g_Qhi[MROWS * EDIM], g_Qlo[MROWS * EDIM];   // A-side of QK^T
__device__ __half g_Khi[MROWS * EDIM];                        // B-side only
__device__ __half g_Vhi[MROWS * EDIM];                        // B-side only
__device__ __half g_Ohi[MROWS * EDIM], g_Olo[MROWS * EDIM];   // A-side of out-proj

// ---------------------------------------------------------------------------
// Primitives
// ---------------------------------------------------------------------------
__device__ __forceinline__ uint32_t smem_u32(const void* p) {
    uint32_t a;
    asm("{ .reg .u64 t; cvta.to.shared.u64 t, %1; cvt.u32.u64 %0, t; }"
        : "=r"(a) : "l"(p));
    return a;
}

#define LDSM_X4(r0, r1, r2, r3, addr) \
    asm volatile("ldmatrix.sync.aligned.m8n8.x4.shared.b16 {%0,%1,%2,%3}, [%4];" \
        : "=r"(r0), "=r"(r1), "=r"(r2), "=r"(r3) : "r"(addr))

#define LDSM_X4T(r0, r1, r2, r3, addr) \
    asm volatile("ldmatrix.sync.aligned.m8n8.x4.trans.shared.b16 {%0,%1,%2,%3}, [%4];" \
        : "=r"(r0), "=r"(r1), "=r"(r2), "=r"(r3) : "r"(addr))

#define CP_ASYNC16(saddr, gptr) \
    asm volatile("cp.async.cg.shared.global [%0], [%1], 16;" \
        :: "r"(saddr), "l"(gptr))

#define CP_COMMIT() asm volatile("cp.async.commit_group;" ::: "memory")
#define CP_WAIT1()  asm volatile("cp.async.wait_group 1;" ::: "memory")
#define CP_WAIT0()  asm volatile("cp.async.wait_group 0;" ::: "memory")

__device__ __forceinline__ void mma_f16(float* c, uint32_t a0, uint32_t a1,
                                        uint32_t a2, uint32_t a3,
                                        uint32_t b0, uint32_t b1) {
    asm volatile(
        "mma.sync.aligned.m16n8k16.row.col.f32.f16.f16.f32 "
        "{%0,%1,%2,%3}, {%4,%5,%6,%7}, {%8,%9}, {%0,%1,%2,%3};"
        : "+f"(c[0]), "+f"(c[1]), "+f"(c[2]), "+f"(c[3])
        : "r"(a0), "r"(a1), "r"(a2), "r"(a3), "r"(b0), "r"(b1));
}

// Split (x,y) into fp16 hi pair + fp16 lo (residual) pair, packed.
__device__ __forceinline__ void split_pack2h(float x, float y,
                                             uint32_t& hi, uint32_t& lo) {
    __half hx = __float2half_rn(x);
    __half hy = __float2half_rn(y);
    __half2 h2 = __halves2half2(hx, hy);
    hi = *(uint32_t*)&h2;
    __half2 l2 = __halves2half2(__float2half_rn(x - __half2float(hx)),
                                __float2half_rn(y - __half2float(hy)));
    lo = *(uint32_t*)&l2;
}

__device__ __forceinline__ uint32_t pack_h2(float x, float y) {
    __half2 t = __floats2half2_rn(x, y);
    return *(uint32_t*)&t;
}

// ---------------------------------------------------------------------------
// Splits: activations hi+lo; weights hi only
// ---------------------------------------------------------------------------
__device__ __forceinline__ void split_body(
    const float* __restrict__ x, __half* __restrict__ hi,
    __half* __restrict__ lo, int n, int bx)
{
    int i = (bx * 256 + threadIdx.x) * 4;
    if (i >= n) return;
    float4 v = *(const float4*)(x + i);
    uint32_t h01, l01, h23, l23;
    split_pack2h(v.x, v.y, h01, l01);
    split_pack2h(v.z, v.w, h23, l23);
    *(uint2*)(hi + i) = make_uint2(h01, h23);
    *(uint2*)(lo + i) = make_uint2(l01, l23);
}

__device__ __forceinline__ void split_hi_body(
    const float* __restrict__ x, __half* __restrict__ hi, int n, int bx)
{
    int i = (bx * 256 + threadIdx.x) * 4;
    if (i >= n) return;
    float4 v = *(const float4*)(x + i);
    *(uint2*)(hi + i) = make_uint2(pack_h2(v.x, v.y), pack_h2(v.z, v.w));
}

__global__ __launch_bounds__(256) void split_all_kernel(
    const float* q, const float* k, const float* v,
    const float* wq, const float* wk, const float* wv, const float* wo)
{
    const int nA = MROWS * EDIM, nW = EDIM * EDIM;
    switch (blockIdx.y) {
        case 0: split_body(q, g_qsh, g_qsl, nA, blockIdx.x); break;
        case 1: split_body(k, g_ksh, g_ksl, nA, blockIdx.x); break;
        case 2: split_body(v, g_vsh, g_vsl, nA, blockIdx.x); break;
        case 3: split_hi_body(wq, g_wqh, nW, blockIdx.x); break;
        case 4: split_hi_body(wk, g_wkh, nW, blockIdx.x); break;
        case 5: split_hi_body(wv, g_wvh, nW, blockIdx.x); break;
        case 6: split_hi_body(wo, g_woh, nW, blockIdx.x); break;
    }
}

// ---------------------------------------------------------------------------
// HMMA fp16x2 GEMM: C = Ahi Whi^T + Alo Whi^T   (fp32 accumulate)
// CTA 128x256, BK=32, 2-stage cp.async, 8 warps each 64x64.
// ---------------------------------------------------------------------------
#define GPAD 40
#define GT_A (128 * GPAD * 2)            // 10240
#define GT_B (256 * GPAD * 2)            // 20480
#define GSTAGE (2 * GT_A + GT_B)         // 40960
#define GSMEM_BYTES (2 * GSTAGE)         // 81920

// Epilogue modes: 0 = write Chi+Clo (scaled), 1 = write Chi only (scaled), 2 = fp32
template <int OUTMODE>
__device__ __forceinline__ void gemm_body(
    const __half* __restrict__ Ahi, const __half* __restrict__ Alo,
    const __half* __restrict__ Whi,
    float* __restrict__ Cf,
    __half* __restrict__ Chi, __half* __restrict__ Clo,
    float scale)
{
    extern __shared__ __half hsm[];
    const uint32_t sb = smem_u32(hsm);

    const int tid = threadIdx.x;
    const int wid = tid >> 5;
    const int lane = tid & 31;
    const int bm = blockIdx.y * 128;
    const int bn = blockIdx.x * 256;
    const int moff = (wid >> 2) * 64;
    const int noff = (wid & 3) * 64;

    float acc[4][8][4];
#pragma unroll
    for (int mt = 0; mt < 4; mt++)
#pragma unroll
        for (int nt = 0; nt < 8; nt++)
#pragma unroll
            for (int r = 0; r < 4; r++) acc[mt][nt][r] = 0.f;

    const uint32_t a_off = ((moff + (lane & 15)) * GPAD + (lane >> 4) * 8) * 2;
    const uint32_t b4_base =
        ((noff + ((lane >> 4) & 1) * 8 + (lane & 7)) * GPAD + ((lane >> 3) & 1) * 8) * 2;

    auto load_stage = [&](int t) {
        const uint32_t s0 = sb + (t & 1) * GSTAGE;
        const int k0 = t * 32;
        // A hi+lo: 1024 chunks -> 4/thread
#pragma unroll
        for (int i = 0; i < 4; i++) {
            int l = i * 256 + tid;
            int tile = l >> 9;
            int r = (l >> 2) & 127;
            int c = (l & 3) * 8;
            const __half* g = (tile ? Alo : Ahi) + (size_t)(bm + r) * EDIM + k0 + c;
            CP_ASYNC16(s0 + tile * GT_A + (uint32_t)(r * GPAD + c) * 2, g);
        }
        // W hi: 1024 chunks -> 4/thread
#pragma unroll
        for (int i = 0; i < 4; i++) {
            int l = i * 256 + tid;
            int r = l >> 2;
            int c = (l & 3) * 8;
            const __half* g = Whi + (size_t)(bn + r) * EDIM + k0 + c;
            CP_ASYNC16(s0 + 2 * GT_A + (uint32_t)(r * GPAD + c) * 2, g);
        }
    };

    const int NT = EDIM / 32;   // 32
    load_stage(0);
    CP_COMMIT();

    for (int t = 0; t < NT; t++) {
        if (t + 1 < NT) {
            load_stage(t + 1);
            CP_COMMIT();
            CP_WAIT1();
        } else {
            CP_WAIT0();
        }
        __syncthreads();

        const uint32_t s0 = sb + (t & 1) * GSTAGE;
        const uint32_t aHiB = s0;
        const uint32_t aLoB = s0 + GT_A;
        const uint32_t wHiB = s0 + 2 * GT_A;

#pragma unroll
        for (int ks = 0; ks < 2; ks++) {
            const uint32_t koff = ks * 32;
            uint32_t ah[4][4], al[4][4];
#pragma unroll
            for (int mt = 0; mt < 4; mt++) {
                LDSM_X4(ah[mt][0], ah[mt][1], ah[mt][2], ah[mt][3],
                        aHiB + a_off + mt * (16 * GPAD * 2) + koff);
                LDSM_X4(al[mt][0], al[mt][1], al[mt][2], al[mt][3],
                        aLoB + a_off + mt * (16 * GPAD * 2) + koff);
            }
#pragma unroll
            for (int ntp = 0; ntp < 4; ntp++) {
                const uint32_t boff = b4_base + ntp * (16 * GPAD * 2) + koff;
                uint32_t b0, b1, b2, b3;
                LDSM_X4(b0, b1, b2, b3, wHiB + boff);
#pragma unroll
                for (int mt = 0; mt < 4; mt++) {
                    mma_f16(acc[mt][2 * ntp],     ah[mt][0], ah[mt][1], ah[mt][2], ah[mt][3], b0, b1);
                    mma_f16(acc[mt][2 * ntp + 1], ah[mt][0], ah[mt][1], ah[mt][2], ah[mt][3], b2, b3);
                }
#pragma unroll
                for (int mt = 0; mt < 4; mt++) {
                    mma_f16(acc[mt][2 * ntp],     al[mt][0], al[mt][1], al[mt][2], al[mt][3], b0, b1);
                    mma_f16(acc[mt][2 * ntp + 1], al[mt][0], al[mt][1], al[mt][2], al[mt][3], b2, b3);
                }
            }
        }
        __syncthreads();
    }

    // Epilogue
#pragma unroll
    for (int mt = 0; mt < 4; mt++) {
#pragma unroll
        for (int nt = 0; nt < 8; nt++) {
            int r0 = bm + moff + mt * 16 + (lane >> 2);
            int c0 = bn + noff + nt * 8 + (lane & 3) * 2;
            if (OUTMODE == 2) {
                *(float2*)(Cf + (size_t)r0 * EDIM + c0) = make_float2(acc[mt][nt][0], acc[mt][nt][1]);
                *(float2*)(Cf + (size_t)(r0 + 8) * EDIM + c0) = make_float2(acc[mt][nt][2], acc[mt][nt][3]);
            } else if (OUTMODE == 0) {
                uint32_t h, l;
                split_pack2h(acc[mt][nt][0] * scale, acc[mt][nt][1] * scale, h, l);
                *(uint32_t*)(Chi + (size_t)r0 * EDIM + c0) = h;
                *(uint32_t*)(Clo + (size_t)r0 * EDIM + c0) = l;
                split_pack2h(acc[mt][nt][2] * scale, acc[mt][nt][3] * scale, h, l);
                *(uint32_t*)(Chi + (size_t)(r0 + 8) * EDIM + c0) = h;
                *(uint32_t*)(Clo + (size_t)(r0 + 8) * EDIM + c0) = l;
            } else {
                *(uint32_t*)(Chi + (size_t)r0 * EDIM + c0) =
                    pack_h2(acc[mt][nt][0], acc[mt][nt][1]);
                *(uint32_t*)(Chi + (size_t)(r0 + 8) * EDIM + c0) =
                    pack_h2(acc[mt][nt][2], acc[mt][nt][3]);
            }
        }
    }
}

// Merged QKV projections: blockIdx.z selects tensor.
__global__ __launch_bounds__(256) void hgemm_qkv()
{
    switch (blockIdx.z) {
        case 0: gemm_body<0>(g_qsh, g_qsl, g_wqh, nullptr, g_Qhi, g_Qlo, QSCALE); break;  // Q: hi+lo, scaled
        case 1: gemm_body<1>(g_ksh, g_ksl, g_wkh, nullptr, g_Khi, nullptr, 1.0f); break;  // K: hi only
        case 2: gemm_body<1>(g_vsh, g_vsl, g_wvh, nullptr, g_Vhi, nullptr, 1.0f); break;  // V: hi only
    }
}

__global__ __launch_bounds__(256) void hgemm_out(float* __restrict__ out)
{
    gemm_body<2>(g_Ohi, g_Olo, g_woh, out, nullptr, nullptr, 1.0f);
}

// ---------------------------------------------------------------------------
// Flash attention, fp16x2. 3-stage cp.async KV ring (Khi, Vhi only).
// smem 92160 -> 2 CTAs/SM (forced). S = Qhi K^T + Qlo K^T; O += Phi V + Plo V.
// ---------------------------------------------------------------------------
#define FPAD 72
#define FQ_BYTES (128 * FPAD * 2)        // 18432
#define FKV_BYTES (64 * FPAD * 2)        // 9216
#define FSTAGE (2 * FKV_BYTES)           // 18432 (Khi, Vhi)
#define FSMEM_BYTES (2 * FQ_BYTES + 3 * FSTAGE)   // 92160

__global__ __launch_bounds__(256, 2) void flash_hmma()
{
    extern __shared__ __half fsm[];
    const uint32_t sb = smem_u32(fsm);
    const uint32_t qHiB = sb;
    const uint32_t qLoB = sb + FQ_BYTES;
    const uint32_t kvB = sb + 2 * FQ_BYTES;

    const int tid = threadIdx.x;
    const int wid = tid >> 5;
    const int lane = tid & 31;
    const int qb = blockIdx.x * 128;
    const int h = blockIdx.y;
    const int b = blockIdx.z;

    const size_t qbase = ((size_t)b * SEQ + qb) * EDIM + h * HDIM;
    const size_t kvbase = (size_t)b * SEQ * EDIM + h * HDIM;

#pragma unroll
    for (int it = 0; it < 4; it++) {
        int l = it * 256 + tid;
        int r = l >> 3;
        int c = (l & 7) * 8;
        *(uint4*)(fsm + r * FPAD + c) = *(const uint4*)(g_Qhi + qbase + (size_t)r * EDIM + c);
        *(uint4*)(fsm + 128 * FPAD + r * FPAD + c) = *(const uint4*)(g_Qlo + qbase + (size_t)r * EDIM + c);
    }

    const int lr = tid >> 3;
    const int lc = (tid & 7) * 8;
    const size_t gKV0 = kvbase + (size_t)lr * EDIM + lc;
    const uint32_t sKV0 = (uint32_t)(lr * FPAD + lc) * 2;
    const uint32_t sKV1 = (uint32_t)((lr + 32) * FPAD + lc) * 2;

    auto load_stage = [&](int t) {
        const uint32_t s0 = kvB + (t % 3) * FSTAGE;
        const size_t g0 = gKV0 + (size_t)t * 64 * EDIM;
        CP_ASYNC16(s0 + sKV0, g_Khi + g0);
        CP_ASYNC16(s0 + sKV1, g_Khi + g0 + (size_t)32 * EDIM);
        CP_ASYNC16(s0 + FKV_BYTES + sKV0, g_Vhi + g0);
        CP_ASYNC16(s0 + FKV_BYTES + sKV1, g_Vhi + g0 + (size_t)32 * EDIM);
    };

    load_stage(0);
    CP_COMMIT();
    load_stage(1);
    CP_COMMIT();
    __syncthreads();

    const uint32_t a_off = ((wid * 16 + (lane & 15)) * FPAD + (lane >> 4) * 8) * 2;
    uint32_t qh[4][4], ql[4][4];
#pragma unroll
    for (int ks = 0; ks < 4; ks++) {
        LDSM_X4(qh[ks][0], qh[ks][1], qh[ks][2], qh[ks][3], qHiB + a_off + ks * 32);
        LDSM_X4(ql[ks][0], ql[ks][1], ql[ks][2], ql[ks][3], qLoB + a_off + ks * 32);
    }

    const uint32_t k4_off =
        ((((lane >> 4) & 1) * 8 + (lane & 7)) * FPAD + ((lane >> 3) & 1) * 8) * 2;
    const uint32_t v4_off =
        (((lane & 7) + ((lane >> 3) & 1) * 8) * FPAD + ((lane >> 4) & 1) * 8) * 2;

    float o[8][4];
#pragma unroll
    for (int nt = 0; nt < 8; nt++)
#pragma unroll
        for (int r = 0; r < 4; r++) o[nt][r] = 0.f;
    float m0 = -1e30f, m1 = -1e30f, l0 = 0.f, l1 = 0.f;

    const int NT = SEQ / 64;   // 32

    for (int t = 0; t < NT; t++) {
        if (t + 1 < NT) CP_WAIT1(); else CP_WAIT0();
        __syncthreads();

        const uint32_t s0 = kvB + (t % 3) * FSTAGE;
        const uint32_t kHiB = s0;
        const uint32_t vHiB = s0 + FKV_BYTES;

        // --- S = Qhi K^T + Qlo K^T ---
        float s[8][4];
#pragma unroll
        for (int nt = 0; nt < 8; nt++)
#pragma unroll
            for (int r = 0; r < 4; r++) s[nt][r] = 0.f;

#pragma unroll
        for (int ks = 0; ks < 4; ks++) {
            const uint32_t koff = ks * 32;
#pragma unroll
            for (int ntp = 0; ntp < 4; ntp++) {
                const uint32_t boff = k4_off + ntp * (16 * FPAD * 2) + koff;
                uint32_t h0, h1, h2, h3;
                LDSM_X4(h0, h1, h2, h3, kHiB + boff);
                mma_f16(s[2 * ntp],     qh[ks][0], qh[ks][1], qh[ks][2], qh[ks][3], h0, h1);
                mma_f16(s[2 * ntp + 1], qh[ks][0], qh[ks][1], qh[ks][2], qh[ks][3], h2, h3);
                mma_f16(s[2 * ntp],     ql[ks][0], ql[ks][1], ql[ks][2], ql[ks][3], h0, h1);
                mma_f16(s[2 * ntp + 1], ql[ks][0], ql[ks][1], ql[ks][2], ql[ks][3], h2, h3);
            }
        }

        // --- online softmax ---
        float mx0 = -1e30f, mx1 = -1e30f;
#pragma unroll
        for (int nt = 0; nt < 8; nt++) {
            mx0 = fmaxf(mx0, fmaxf(s[nt][0], s[nt][1]));
            mx1 = fmaxf(mx1, fmaxf(s[nt][2], s[nt][3]));
        }
        mx0 = fmaxf(mx0, __shfl_xor_sync(0xffffffffu, mx0, 1));
        mx0 = fmaxf(mx0, __shfl_xor_sync(0xffffffffu, mx0, 2));
        mx1 = fmaxf(mx1, __shfl_xor_sync(0xffffffffu, mx1, 1));
        mx1 = fmaxf(mx1, __shfl_xor_sync(0xffffffffu, mx1, 2));

        float mn0 = fmaxf(m0, mx0), mn1 = fmaxf(m1, mx1);
        float al0 = __expf(m0 - mn0), al1 = __expf(m1 - mn1);
        m0 = mn0; m1 = mn1;

        float sum0 = 0.f, sum1 = 0.f;
#pragma unroll
        for (int nt = 0; nt < 8; nt++) {
            s[nt][0] = __expf(s[nt][0] - mn0);
            s[nt][1] = __expf(s[nt][1] - mn0);
            s[nt][2] = __expf(s[nt][2] - mn1);
            s[nt][3] = __expf(s[nt][3] - mn1);
            sum0 += s[nt][0] + s[nt][1];
            sum1 += s[nt][2] + s[nt][3];
        }
        sum0 += __shfl_xor_sync(0xffffffffu, sum0, 1);
        sum0 += __shfl_xor_sync(0xffffffffu, sum0, 2);
        sum1 += __shfl_xor_sync(0xffffffffu, sum1, 1);
        sum1 += __shfl_xor_sync(0xffffffffu, sum1, 2);
        l0 = l0 * al0 + sum0;
        l1 = l1 * al1 + sum1;

#pragma unroll
        for (int nt = 0; nt < 8; nt++) {
            o[nt][0] *= al0; o[nt][1] *= al0;
            o[nt][2] *= al1; o[nt][3] *= al1;
        }

        // --- O += Phi V + Plo V ---
#pragma unroll
        for (int kt = 0; kt < 4; kt++) {
            uint32_t ph[4], pl[4];
            split_pack2h(s[2 * kt][0],     s[2 * kt][1],     ph[0], pl[0]);
            split_pack2h(s[2 * kt][2],     s[2 * kt][3],     ph[1], pl[1]);
            split_pack2h(s[2 * kt + 1][0], s[2 * kt + 1][1], ph[2], pl[2]);
            split_pack2h(s[2 * kt + 1][2], s[2 * kt + 1][3], ph[3], pl[3]);
#pragma unroll
            for (int ntp = 0; ntp < 4; ntp++) {
                const uint32_t voff = v4_off + kt * (16 * FPAD * 2) + ntp * 32;
                uint32_t vh0, vh1, vh2, vh3;
                LDSM_X4T(vh0, vh1, vh2, vh3, vHiB + voff);
                mma_f16(o[2 * ntp],     ph[0], ph[1], ph[2], ph[3], vh0, vh1);
                mma_f16(o[2 * ntp + 1], ph[0], ph[1], ph[2], ph[3], vh2, vh3);
                mma_f16(o[2 * ntp],     pl[0], pl[1], pl[2], pl[3], vh0, vh1);
                mma_f16(o[2 * ntp + 1], pl[0], pl[1], pl[2], pl[3], vh2, vh3);
            }
        }

        if (t + 2 < NT) {
            load_stage(t + 2);
            CP_COMMIT();
        }
    }

    // Epilogue: normalize, split, store pre-split fp16 hi/lo
    const int r0 = qb + wid * 16 + (lane >> 2);
    float inv0 = 1.f / l0, inv1 = 1.f / l1;
    const size_t obase = ((size_t)b * SEQ + r0) * EDIM + h * HDIM;
#pragma unroll
    for (int nt = 0; nt < 8; nt++) {
        int c = nt * 8 + (lane & 3) * 2;
        uint32_t hh, ll;
        split_pack2h(o[nt][0] * inv0, o[nt][1] * inv0, hh, ll);
        *(uint32_t*)(g_Ohi + obase + c) = hh;
        *(uint32_t*)(g_Olo + obase + c) = ll;
        split_pack2h(o[nt][2] * inv1, o[nt][3] * inv1, hh, ll);
        *(uint32_t*)(g_Ohi + obase + (size_t)8 * EDIM + c) = hh;
        *(uint32_t*)(g_Olo + obase + (size_t)8 * EDIM + c) = ll;
    }
}

// ---------------------------------------------------------------------------
// Launch: 4 kernels total
// ---------------------------------------------------------------------------
extern "C" void kernel_launch(void* const* d_in, const int* in_sizes, int n_in,
                              void* d_out, int out_size)
{
    (void)in_sizes; (void)n_in; (void)out_size;
    const float* q  = (const float*)d_in[0];
    const float* k  = (const float*)d_in[1];
    const float* v  = (const float*)d_in[2];
    const float* Wq = (const float*)d_in[3];
    const float* Wk = (const float*)d_in[4];
    const float* Wv = (const float*)d_in[5];
    const float* Wo = (const float*)d_in[6];
    float* out = (float*)d_out;

    static int attr_set = 0;
    if (!attr_set) {
        cudaFuncSetAttribute(hgemm_qkv,
                             cudaFuncAttributeMaxDynamicSharedMemorySize, GSMEM_BYTES);
        cudaFuncSetAttribute(hgemm_out,
                             cudaFuncAttributeMaxDynamicSharedMemorySize, GSMEM_BYTES);
        cudaFuncSetAttribute(flash_hmma,
                             cudaFuncAttributeMaxDynamicSharedMemorySize, FSMEM_BYTES);
        attr_set = 1;
    }

    const int nA = MROWS * EDIM;

    // 1) Split inputs: activations hi+lo, weights hi only
    dim3 sgrid(nA / 1024, 7);
    split_all_kernel<<<sgrid, 256>>>(q, k, v, Wq, Wk, Wv, Wo);

    // 2) Merged QKV projections
    dim3 qkvgrid(EDIM / 256, MROWS / 128, 3);
    hgemm_qkv<<<qkvgrid, 256, GSMEM_BYTES>>>();

    // 3) Flash attention
    dim3 fgrid(SEQ / 128, NHEADS, BATCH);
    flash_hmma<<<fgrid, 256, FSMEM_BYTES>>>();

    // 4) Output projection
    dim3 ogrid(EDIM / 256, MROWS / 128);
    hgemm_out<<<ogrid, 256, GSMEM_BYTES>>>(out);
}

// round 9
// speedup vs baseline: 2.3455x; 1.5601x over previous
#include <cuda_runtime.h>
#include <cuda_fp16.h>
#include <cstdint>

// Problem constants
#define EDIM 1024
#define BATCH 2
#define SEQ 2048
#define NHEADS 16
#define HDIM 64
#define MROWS (BATCH * SEQ)          // 4096
#define QSCALE 0.125f                // 1/sqrt(64), exact power of two

// ---------------------------------------------------------------------------
// Scratch (allocation-free). Pure fp16 single-pass everywhere.
// ---------------------------------------------------------------------------
__device__ __half g_qs[MROWS * EDIM];
__device__ __half g_ks[MROWS * EDIM];
__device__ __half g_vs[MROWS * EDIM];
__device__ __half g_wq[EDIM * EDIM];
__device__ __half g_wk[EDIM * EDIM];
__device__ __half g_wv[EDIM * EDIM];
__device__ __half g_wo[EDIM * EDIM];
__device__ __half g_Q[MROWS * EDIM];     // pre-scaled by 1/8
__device__ __half g_K[MROWS * EDIM];
__device__ __half g_V[MROWS * EDIM];
__device__ __half g_Oh[MROWS * EDIM];

// ---------------------------------------------------------------------------
// Primitives
// ---------------------------------------------------------------------------
__device__ __forceinline__ uint32_t smem_u32(const void* p) {
    uint32_t a;
    asm("{ .reg .u64 t; cvta.to.shared.u64 t, %1; cvt.u32.u64 %0, t; }"
        : "=r"(a) : "l"(p));
    return a;
}

#define LDSM_X4(r0, r1, r2, r3, addr) \
    asm volatile("ldmatrix.sync.aligned.m8n8.x4.shared.b16 {%0,%1,%2,%3}, [%4];" \
        : "=r"(r0), "=r"(r1), "=r"(r2), "=r"(r3) : "r"(addr))

#define LDSM_X4T(r0, r1, r2, r3, addr) \
    asm volatile("ldmatrix.sync.aligned.m8n8.x4.trans.shared.b16 {%0,%1,%2,%3}, [%4];" \
        : "=r"(r0), "=r"(r1), "=r"(r2), "=r"(r3) : "r"(addr))

#define CP_ASYNC16(saddr, gptr) \
    asm volatile("cp.async.cg.shared.global [%0], [%1], 16;" \
        :: "r"(saddr), "l"(gptr))

#define CP_COMMIT() asm volatile("cp.async.commit_group;" ::: "memory")
#define CP_WAIT1()  asm volatile("cp.async.wait_group 1;" ::: "memory")
#define CP_WAIT0()  asm volatile("cp.async.wait_group 0;" ::: "memory")

__device__ __forceinline__ void mma_f16(float* c, uint32_t a0, uint32_t a1,
                                        uint32_t a2, uint32_t a3,
                                        uint32_t b0, uint32_t b1) {
    asm volatile(
        "mma.sync.aligned.m16n8k16.row.col.f32.f16.f16.f32 "
        "{%0,%1,%2,%3}, {%4,%5,%6,%7}, {%8,%9}, {%0,%1,%2,%3};"
        : "+f"(c[0]), "+f"(c[1]), "+f"(c[2]), "+f"(c[3])
        : "r"(a0), "r"(a1), "r"(a2), "r"(a3), "r"(b0), "r"(b1));
}

__device__ __forceinline__ uint32_t pack_h2(float x, float y) {
    __half2 t = __floats2half2_rn(x, y);
    return *(uint32_t*)&t;
}

// ---------------------------------------------------------------------------
// Convert all 7 inputs to fp16 (single precision pass)
// ---------------------------------------------------------------------------
__device__ __forceinline__ void cvt_body(
    const float* __restrict__ x, __half* __restrict__ hi, int n, int bx)
{
    int i = (bx * 256 + threadIdx.x) * 4;
    if (i >= n) return;
    float4 v = *(const float4*)(x + i);
    *(uint2*)(hi + i) = make_uint2(pack_h2(v.x, v.y), pack_h2(v.z, v.w));
}

__global__ __launch_bounds__(256) void cvt_all_kernel(
    const float* q, const float* k, const float* v,
    const float* wq, const float* wk, const float* wv, const float* wo)
{
    const int nA = MROWS * EDIM, nW = EDIM * EDIM;
    switch (blockIdx.y) {
        case 0: cvt_body(q,  g_qs, nA, blockIdx.x); break;
        case 1: cvt_body(k,  g_ks, nA, blockIdx.x); break;
        case 2: cvt_body(v,  g_vs, nA, blockIdx.x); break;
        case 3: cvt_body(wq, g_wq, nW, blockIdx.x); break;
        case 4: cvt_body(wk, g_wk, nW, blockIdx.x); break;
        case 5: cvt_body(wv, g_wv, nW, blockIdx.x); break;
        case 6: cvt_body(wo, g_wo, nW, blockIdx.x); break;
    }
}

// ---------------------------------------------------------------------------
// Pure fp16 HMMA GEMM: C[M,N] = A W^T  (fp32 accumulate)
// CTA 128x256, BK=32, 2-stage cp.async, 8 warps each 64x64.
// ---------------------------------------------------------------------------
#define GPAD 40
#define GT_A (128 * GPAD * 2)            // 10240
#define GT_B (256 * GPAD * 2)            // 20480
#define GSTAGE (GT_A + GT_B)             // 30720
#define GSMEM_BYTES (2 * GSTAGE)         // 61440

// OUTMODE: 1 = fp16 out (scaled), 2 = fp32 out
template <int OUTMODE>
__device__ __forceinline__ void gemm_body(
    const __half* __restrict__ A, const __half* __restrict__ W,
    float* __restrict__ Cf, __half* __restrict__ Ch, float scale)
{
    extern __shared__ __half hsm[];
    const uint32_t sb = smem_u32(hsm);

    const int tid = threadIdx.x;
    const int wid = tid >> 5;
    const int lane = tid & 31;
    const int bm = blockIdx.y * 128;
    const int bn = blockIdx.x * 256;
    const int moff = (wid >> 2) * 64;
    const int noff = (wid & 3) * 64;

    float acc[4][8][4];
#pragma unroll
    for (int mt = 0; mt < 4; mt++)
#pragma unroll
        for (int nt = 0; nt < 8; nt++)
#pragma unroll
            for (int r = 0; r < 4; r++) acc[mt][nt][r] = 0.f;

    const uint32_t a_off = ((moff + (lane & 15)) * GPAD + (lane >> 4) * 8) * 2;
    const uint32_t b4_base =
        ((noff + ((lane >> 4) & 1) * 8 + (lane & 7)) * GPAD + ((lane >> 3) & 1) * 8) * 2;

    auto load_stage = [&](int t) {
        const uint32_t s0 = sb + (t & 1) * GSTAGE;
        const int k0 = t * 32;
        // A: 128 rows x 4 chunks = 512 -> 2/thread
#pragma unroll
        for (int i = 0; i < 2; i++) {
            int l = i * 256 + tid;
            int r = l >> 2;
            int c = (l & 3) * 8;
            CP_ASYNC16(s0 + (uint32_t)(r * GPAD + c) * 2,
                       A + (size_t)(bm + r) * EDIM + k0 + c);
        }
        // B: 256 rows x 4 chunks = 1024 -> 4/thread
#pragma unroll
        for (int i = 0; i < 4; i++) {
            int l = i * 256 + tid;
            int r = l >> 2;
            int c = (l & 3) * 8;
            CP_ASYNC16(s0 + GT_A + (uint32_t)(r * GPAD + c) * 2,
                       W + (size_t)(bn + r) * EDIM + k0 + c);
        }
    };

    const int NT = EDIM / 32;   // 32
    load_stage(0);
    CP_COMMIT();

    for (int t = 0; t < NT; t++) {
        if (t + 1 < NT) {
            load_stage(t + 1);
            CP_COMMIT();
            CP_WAIT1();
        } else {
            CP_WAIT0();
        }
        __syncthreads();

        const uint32_t s0 = sb + (t & 1) * GSTAGE;
        const uint32_t aB = s0;
        const uint32_t wB = s0 + GT_A;

#pragma unroll
        for (int ks = 0; ks < 2; ks++) {
            const uint32_t koff = ks * 32;
            uint32_t ah[4][4];
#pragma unroll
            for (int mt = 0; mt < 4; mt++)
                LDSM_X4(ah[mt][0], ah[mt][1], ah[mt][2], ah[mt][3],
                        aB + a_off + mt * (16 * GPAD * 2) + koff);
#pragma unroll
            for (int ntp = 0; ntp < 4; ntp++) {
                const uint32_t boff = b4_base + ntp * (16 * GPAD * 2) + koff;
                uint32_t b0, b1, b2, b3;
                LDSM_X4(b0, b1, b2, b3, wB + boff);
#pragma unroll
                for (int mt = 0; mt < 4; mt++) {
                    mma_f16(acc[mt][2 * ntp],     ah[mt][0], ah[mt][1], ah[mt][2], ah[mt][3], b0, b1);
                    mma_f16(acc[mt][2 * ntp + 1], ah[mt][0], ah[mt][1], ah[mt][2], ah[mt][3], b2, b3);
                }
            }
        }
        __syncthreads();
    }

    // Epilogue
#pragma unroll
    for (int mt = 0; mt < 4; mt++) {
#pragma unroll
        for (int nt = 0; nt < 8; nt++) {
            int r0 = bm + moff + mt * 16 + (lane >> 2);
            int c0 = bn + noff + nt * 8 + (lane & 3) * 2;
            if (OUTMODE == 2) {
                *(float2*)(Cf + (size_t)r0 * EDIM + c0) = make_float2(acc[mt][nt][0], acc[mt][nt][1]);
                *(float2*)(Cf + (size_t)(r0 + 8) * EDIM + c0) = make_float2(acc[mt][nt][2], acc[mt][nt][3]);
            } else {
                *(uint32_t*)(Ch + (size_t)r0 * EDIM + c0) =
                    pack_h2(acc[mt][nt][0] * scale, acc[mt][nt][1] * scale);
                *(uint32_t*)(Ch + (size_t)(r0 + 8) * EDIM + c0) =
                    pack_h2(acc[mt][nt][2] * scale, acc[mt][nt][3] * scale);
            }
        }
    }
}

__global__ __launch_bounds__(256) void hgemm_qkv()
{
    switch (blockIdx.z) {
        case 0: gemm_body<1>(g_qs, g_wq, nullptr, g_Q, QSCALE); break;
        case 1: gemm_body<1>(g_ks, g_wk, nullptr, g_K, 1.0f); break;
        case 2: gemm_body<1>(g_vs, g_wv, nullptr, g_V, 1.0f); break;
    }
}

__global__ __launch_bounds__(256) void hgemm_out(float* __restrict__ out)
{
    gemm_body<2>(g_Oh, g_wo, out, nullptr, 1.0f);
}

// ---------------------------------------------------------------------------
// Flash attention, pure fp16. 3-stage cp.async KV ring.
// CTA 128 q-rows; 8 warps x 16 rows; 64-row KV stages; 2 CTAs/SM.
// ---------------------------------------------------------------------------
#define FPAD 72
#define FQ_BYTES (128 * FPAD * 2)        // 18432
#define FKV_BYTES (64 * FPAD * 2)        // 9216
#define FSTAGE (2 * FKV_BYTES)           // 18432 (K, V)
#define FSMEM_BYTES (FQ_BYTES + 3 * FSTAGE)   // 73728

__global__ __launch_bounds__(256, 2) void flash_hmma()
{
    extern __shared__ __half fsm[];
    const uint32_t sb = smem_u32(fsm);
    const uint32_t qB = sb;
    const uint32_t kvB = sb + FQ_BYTES;

    const int tid = threadIdx.x;
    const int wid = tid >> 5;
    const int lane = tid & 31;
    const int qb = blockIdx.x * 128;
    const int h = blockIdx.y;
    const int b = blockIdx.z;

    const size_t qbase = ((size_t)b * SEQ + qb) * EDIM + h * HDIM;
    const size_t kvbase = (size_t)b * SEQ * EDIM + h * HDIM;

    // Q tile -> smem
#pragma unroll
    for (int it = 0; it < 2; it++) {
        int l = it * 256 + tid;
        int r = l >> 2;
        int c = (l & 3) * 16;
        // 128 rows x 64 cols = 8192 halves = 512 chunks of 16 halves? use 8-half chunks:
        // simpler: 1024 chunks of 8 halves -> 4 iters. Redo below.
        (void)r; (void)c;
    }
#pragma unroll
    for (int it = 0; it < 4; it++) {
        int l = it * 256 + tid;     // 0..1023
        int r = l >> 3;
        int c = (l & 7) * 8;
        *(uint4*)(fsm + r * FPAD + c) = *(const uint4*)(g_Q + qbase + (size_t)r * EDIM + c);
    }

    const int lr = tid >> 3;
    const int lc = (tid & 7) * 8;
    const size_t gKV0 = kvbase + (size_t)lr * EDIM + lc;
    const uint32_t sKV0 = (uint32_t)(lr * FPAD + lc) * 2;
    const uint32_t sKV1 = (uint32_t)((lr + 32) * FPAD + lc) * 2;

    auto load_stage = [&](int t) {
        const uint32_t s0 = kvB + (t % 3) * FSTAGE;
        const size_t g0 = gKV0 + (size_t)t * 64 * EDIM;
        CP_ASYNC16(s0 + sKV0, g_K + g0);
        CP_ASYNC16(s0 + sKV1, g_K + g0 + (size_t)32 * EDIM);
        CP_ASYNC16(s0 + FKV_BYTES + sKV0, g_V + g0);
        CP_ASYNC16(s0 + FKV_BYTES + sKV1, g_V + g0 + (size_t)32 * EDIM);
    };

    load_stage(0);
    CP_COMMIT();
    load_stage(1);
    CP_COMMIT();
    __syncthreads();

    // Hoist Q fragments
    const uint32_t a_off = ((wid * 16 + (lane & 15)) * FPAD + (lane >> 4) * 8) * 2;
    uint32_t qh[4][4];
#pragma unroll
    for (int ks = 0; ks < 4; ks++)
        LDSM_X4(qh[ks][0], qh[ks][1], qh[ks][2], qh[ks][3], qB + a_off + ks * 32);

    const uint32_t k4_off =
        ((((lane >> 4) & 1) * 8 + (lane & 7)) * FPAD + ((lane >> 3) & 1) * 8) * 2;
    const uint32_t v4_off =
        (((lane & 7) + ((lane >> 3) & 1) * 8) * FPAD + ((lane >> 4) & 1) * 8) * 2;

    float o[8][4];
#pragma unroll
    for (int nt = 0; nt < 8; nt++)
#pragma unroll
        for (int r = 0; r < 4; r++) o[nt][r] = 0.f;
    float m0 = -1e30f, m1 = -1e30f, l0 = 0.f, l1 = 0.f;

    const int NT = SEQ / 64;   // 32

    for (int t = 0; t < NT; t++) {
        if (t + 1 < NT) CP_WAIT1(); else CP_WAIT0();
        __syncthreads();

        const uint32_t s0 = kvB + (t % 3) * FSTAGE;
        const uint32_t kB = s0;
        const uint32_t vB = s0 + FKV_BYTES;

        // --- S = Q K^T (single pass) ---
        float s[8][4];
#pragma unroll
        for (int nt = 0; nt < 8; nt++)
#pragma unroll
            for (int r = 0; r < 4; r++) s[nt][r] = 0.f;

#pragma unroll
        for (int ks = 0; ks < 4; ks++) {
            const uint32_t koff = ks * 32;
#pragma unroll
            for (int ntp = 0; ntp < 4; ntp++) {
                const uint32_t boff = k4_off + ntp * (16 * FPAD * 2) + koff;
                uint32_t h0, h1, h2, h3;
                LDSM_X4(h0, h1, h2, h3, kB + boff);
                mma_f16(s[2 * ntp],     qh[ks][0], qh[ks][1], qh[ks][2], qh[ks][3], h0, h1);
                mma_f16(s[2 * ntp + 1], qh[ks][0], qh[ks][1], qh[ks][2], qh[ks][3], h2, h3);
            }
        }

        // --- online softmax ---
        float mx0 = -1e30f, mx1 = -1e30f;
#pragma unroll
        for (int nt = 0; nt < 8; nt++) {
            mx0 = fmaxf(mx0, fmaxf(s[nt][0], s[nt][1]));
            mx1 = fmaxf(mx1, fmaxf(s[nt][2], s[nt][3]));
        }
        mx0 = fmaxf(mx0, __shfl_xor_sync(0xffffffffu, mx0, 1));
        mx0 = fmaxf(mx0, __shfl_xor_sync(0xffffffffu, mx0, 2));
        mx1 = fmaxf(mx1, __shfl_xor_sync(0xffffffffu, mx1, 1));
        mx1 = fmaxf(mx1, __shfl_xor_sync(0xffffffffu, mx1, 2));

        float mn0 = fmaxf(m0, mx0), mn1 = fmaxf(m1, mx1);
        float al0 = __expf(m0 - mn0), al1 = __expf(m1 - mn1);
        m0 = mn0; m1 = mn1;

        float sum0 = 0.f, sum1 = 0.f;
#pragma unroll
        for (int nt = 0; nt < 8; nt++) {
            s[nt][0] = __expf(s[nt][0] - mn0);
            s[nt][1] = __expf(s[nt][1] - mn0);
            s[nt][2] = __expf(s[nt][2] - mn1);
            s[nt][3] = __expf(s[nt][3] - mn1);
            sum0 += s[nt][0] + s[nt][1];
            sum1 += s[nt][2] + s[nt][3];
        }
        sum0 += __shfl_xor_sync(0xffffffffu, sum0, 1);
        sum0 += __shfl_xor_sync(0xffffffffu, sum0, 2);
        sum1 += __shfl_xor_sync(0xffffffffu, sum1, 1);
        sum1 += __shfl_xor_sync(0xffffffffu, sum1, 2);
        l0 = l0 * al0 + sum0;
        l1 = l1 * al1 + sum1;

#pragma unroll
        for (int nt = 0; nt < 8; nt++) {
            o[nt][0] *= al0; o[nt][1] *= al0;
            o[nt][2] *= al1; o[nt][3] *= al1;
        }

        // --- O += P V (single pass) ---
#pragma unroll
        for (int kt = 0; kt < 4; kt++) {
            uint32_t ph[4];
            ph[0] = pack_h2(s[2 * kt][0],     s[2 * kt][1]);
            ph[1] = pack_h2(s[2 * kt][2],     s[2 * kt][3]);
            ph[2] = pack_h2(s[2 * kt + 1][0], s[2 * kt + 1][1]);
            ph[3] = pack_h2(s[2 * kt + 1][2], s[2 * kt + 1][3]);
#pragma unroll
            for (int ntp = 0; ntp < 4; ntp++) {
                const uint32_t voff = v4_off + kt * (16 * FPAD * 2) + ntp * 32;
                uint32_t vh0, vh1, vh2, vh3;
                LDSM_X4T(vh0, vh1, vh2, vh3, vB + voff);
                mma_f16(o[2 * ntp],     ph[0], ph[1], ph[2], ph[3], vh0, vh1);
                mma_f16(o[2 * ntp + 1], ph[0], ph[1], ph[2], ph[3], vh2, vh3);
            }
        }

        if (t + 2 < NT) {
            load_stage(t + 2);
            CP_COMMIT();
        }
    }

    // Epilogue: normalize, store fp16
    const int r0 = qb + wid * 16 + (lane >> 2);
    float inv0 = 1.f / l0, inv1 = 1.f / l1;
    const size_t obase = ((size_t)b * SEQ + r0) * EDIM + h * HDIM;
#pragma unroll
    for (int nt = 0; nt < 8; nt++) {
        int c = nt * 8 + (lane & 3) * 2;
        *(uint32_t*)(g_Oh + obase + c) = pack_h2(o[nt][0] * inv0, o[nt][1] * inv0);
        *(uint32_t*)(g_Oh + obase + (size_t)8 * EDIM + c) = pack_h2(o[nt][2] * inv1, o[nt][3] * inv1);
    }
}

// ---------------------------------------------------------------------------
// Launch: 4 kernels total
// ---------------------------------------------------------------------------
extern "C" void kernel_launch(void* const* d_in, const int* in_sizes, int n_in,
                              void* d_out, int out_size)
{
    (void)in_sizes; (void)n_in; (void)out_size;
    const float* q  = (const float*)d_in[0];
    const float* k  = (const float*)d_in[1];
    const float* v  = (const float*)d_in[2];
    const float* Wq = (const float*)d_in[3];
    const float* Wk = (const float*)d_in[4];
    const float* Wv = (const float*)d_in[5];
    const float* Wo = (const float*)d_in[6];
    float* out = (float*)d_out;

    static int attr_set = 0;
    if (!attr_set) {
        cudaFuncSetAttribute(hgemm_qkv,
                             cudaFuncAttributeMaxDynamicSharedMemorySize, GSMEM_BYTES);
        cudaFuncSetAttribute(hgemm_out,
                             cudaFuncAttributeMaxDynamicSharedMemorySize, GSMEM_BYTES);
        cudaFuncSetAttribute(flash_hmma,
                             cudaFuncAttributeMaxDynamicSharedMemorySize, FSMEM_BYTES);
        attr_set = 1;
    }

    const int nA = MROWS * EDIM;

    // 1) Convert all inputs to fp16
    dim3 sgrid(nA / 1024, 7);
    cvt_all_kernel<<<sgrid, 256>>>(q, k, v, Wq, Wk, Wv, Wo);

    // 2) Merged QKV projections
    dim3 qkvgrid(EDIM / 256, MROWS / 128, 3);
    hgemm_qkv<<<qkvgrid, 256, GSMEM_BYTES>>>();

    // 3) Flash attention
    dim3 fgrid(SEQ / 128, NHEADS, BATCH);
    flash_hmma<<<fgrid, 256, FSMEM_BYTES>>>();

    // 4) Output projection
    dim3 ogrid(EDIM / 256, MROWS / 128);
    hgemm_out<<<ogrid, 256, GSMEM_BYTES>>>(out);
}

// round 10
// speedup vs baseline: 2.6331x; 1.1226x over previous
#include <cuda_runtime.h>
#include <cuda_fp16.h>
#include <cstdint>

// Problem constants
#define EDIM 1024
#define BATCH 2
#define SEQ 2048
#define NHEADS 16
#define HDIM 64
#define MROWS (BATCH * SEQ)          // 4096
// 1/sqrt(64) * log2(e): softmax computed in log2 domain (exp2f = raw MUFU.EX2)
#define QSCALE_LOG2 (0.125f * 1.4426950408889634f)

// ---------------------------------------------------------------------------
// Scratch (allocation-free). Pure fp16 single-pass everywhere.
// ---------------------------------------------------------------------------
__device__ __half g_qs[MROWS * EDIM];
__device__ __half g_ks[MROWS * EDIM];
__device__ __half g_vs[MROWS * EDIM];
__device__ __half g_wq[EDIM * EDIM];
__device__ __half g_wk[EDIM * EDIM];
__device__ __half g_wv[EDIM * EDIM];
__device__ __half g_wo[EDIM * EDIM];
__device__ __half g_Q[MROWS * EDIM];     // pre-scaled by QSCALE_LOG2
__device__ __half g_K[MROWS * EDIM];
__device__ __half g_V[MROWS * EDIM];
__device__ __half g_Oh[MROWS * EDIM];

// ---------------------------------------------------------------------------
// Primitives
// ---------------------------------------------------------------------------
__device__ __forceinline__ uint32_t smem_u32(const void* p) {
    uint32_t a;
    asm("{ .reg .u64 t; cvta.to.shared.u64 t, %1; cvt.u32.u64 %0, t; }"
        : "=r"(a) : "l"(p));
    return a;
}

#define LDSM_X4(r0, r1, r2, r3, addr) \
    asm volatile("ldmatrix.sync.aligned.m8n8.x4.shared.b16 {%0,%1,%2,%3}, [%4];" \
        : "=r"(r0), "=r"(r1), "=r"(r2), "=r"(r3) : "r"(addr))

#define LDSM_X4T(r0, r1, r2, r3, addr) \
    asm volatile("ldmatrix.sync.aligned.m8n8.x4.trans.shared.b16 {%0,%1,%2,%3}, [%4];" \
        : "=r"(r0), "=r"(r1), "=r"(r2), "=r"(r3) : "r"(addr))

#define CP_ASYNC16(saddr, gptr) \
    asm volatile("cp.async.cg.shared.global [%0], [%1], 16;" \
        :: "r"(saddr), "l"(gptr))

#define CP_COMMIT() asm volatile("cp.async.commit_group;" ::: "memory")
#define CP_WAIT2()  asm volatile("cp.async.wait_group 2;" ::: "memory")
#define CP_WAIT1()  asm volatile("cp.async.wait_group 1;" ::: "memory")
#define CP_WAIT0()  asm volatile("cp.async.wait_group 0;" ::: "memory")

__device__ __forceinline__ void mma_f16(float* c, uint32_t a0, uint32_t a1,
                                        uint32_t a2, uint32_t a3,
                                        uint32_t b0, uint32_t b1) {
    asm volatile(
        "mma.sync.aligned.m16n8k16.row.col.f32.f16.f16.f32 "
        "{%0,%1,%2,%3}, {%4,%5,%6,%7}, {%8,%9}, {%0,%1,%2,%3};"
        : "+f"(c[0]), "+f"(c[1]), "+f"(c[2]), "+f"(c[3])
        : "r"(a0), "r"(a1), "r"(a2), "r"(a3), "r"(b0), "r"(b1));
}

__device__ __forceinline__ uint32_t pack_h2(float x, float y) {
    __half2 t = __floats2half2_rn(x, y);
    return *(uint32_t*)&t;
}

// ---------------------------------------------------------------------------
// Convert all 7 inputs to fp16
// ---------------------------------------------------------------------------
__device__ __forceinline__ void cvt_body(
    const float* __restrict__ x, __half* __restrict__ hi, int n, int bx)
{
    int i = (bx * 256 + threadIdx.x) * 4;
    if (i >= n) return;
    float4 v = *(const float4*)(x + i);
    *(uint2*)(hi + i) = make_uint2(pack_h2(v.x, v.y), pack_h2(v.z, v.w));
}

__global__ __launch_bounds__(256) void cvt_all_kernel(
    const float* q, const float* k, const float* v,
    const float* wq, const float* wk, const float* wv, const float* wo)
{
    const int nA = MROWS * EDIM, nW = EDIM * EDIM;
    switch (blockIdx.y) {
        case 0: cvt_body(q,  g_qs, nA, blockIdx.x); break;
        case 1: cvt_body(k,  g_ks, nA, blockIdx.x); break;
        case 2: cvt_body(v,  g_vs, nA, blockIdx.x); break;
        case 3: cvt_body(wq, g_wq, nW, blockIdx.x); break;
        case 4: cvt_body(wk, g_wk, nW, blockIdx.x); break;
        case 5: cvt_body(wv, g_wv, nW, blockIdx.x); break;
        case 6: cvt_body(wo, g_wo, nW, blockIdx.x); break;
    }
}

// ---------------------------------------------------------------------------
// fp16 HMMA GEMM: C[M,N] = A W^T, fp32 accumulate.
// CTA 128x128, BK=32, 3-stage cp.async ring (1 sync/iter), 8 warps (64x32),
// 2 CTAs/SM for latency hiding.
// ---------------------------------------------------------------------------
#define GPAD 40
#define GT_A (128 * GPAD * 2)            // 10240 (A tile = B tile size)
#define GSTAGE (2 * GT_A)                // 20480
#define GSMEM_BYTES (3 * GSTAGE)         // 61440 -> 2 CTAs/SM

// OUTMODE: 1 = fp16 out (scaled), 2 = fp32 out
template <int OUTMODE>
__device__ __forceinline__ void gemm_body(
    const __half* __restrict__ A, const __half* __restrict__ W,
    float* __restrict__ Cf, __half* __restrict__ Ch, float scale)
{
    extern __shared__ __half hsm[];
    const uint32_t sb = smem_u32(hsm);

    const int tid = threadIdx.x;
    const int wid = tid >> 5;
    const int lane = tid & 31;
    const int bm = blockIdx.y * 128;
    const int bn = blockIdx.x * 128;
    const int moff = (wid >> 2) * 64;   // 0 or 64
    const int noff = (wid & 3) * 32;    // 0..96

    float acc[4][4][4];
#pragma unroll
    for (int mt = 0; mt < 4; mt++)
#pragma unroll
        for (int nt = 0; nt < 4; nt++)
#pragma unroll
            for (int r = 0; r < 4; r++) acc[mt][nt][r] = 0.f;

    const uint32_t a_off = ((moff + (lane & 15)) * GPAD + (lane >> 4) * 8) * 2;
    const uint32_t b4_base =
        ((noff + ((lane >> 4) & 1) * 8 + (lane & 7)) * GPAD + ((lane >> 3) & 1) * 8) * 2;

    auto load_stage = [&](int t) {
        const uint32_t s0 = sb + (t % 3) * GSTAGE;
        const int k0 = t * 32;
        // A: 128 rows x 4 chunks = 512 -> 2/thread; B same
#pragma unroll
        for (int i = 0; i < 2; i++) {
            int l = i * 256 + tid;
            int r = l >> 2;
            int c = (l & 3) * 8;
            CP_ASYNC16(s0 + (uint32_t)(r * GPAD + c) * 2,
                       A + (size_t)(bm + r) * EDIM + k0 + c);
            CP_ASYNC16(s0 + GT_A + (uint32_t)(r * GPAD + c) * 2,
                       W + (size_t)(bn + r) * EDIM + k0 + c);
        }
    };

    const int NT = EDIM / 32;   // 32
    load_stage(0);
    CP_COMMIT();
    load_stage(1);
    CP_COMMIT();

    for (int t = 0; t < NT; t++) {
        // pending after stage t completes: min(1, NT-1-t)
        if (t < NT - 1) CP_WAIT1(); else CP_WAIT0();
        __syncthreads();

        const uint32_t s0 = sb + (t % 3) * GSTAGE;
        const uint32_t aB = s0;
        const uint32_t wB = s0 + GT_A;

#pragma unroll
        for (int ks = 0; ks < 2; ks++) {
            const uint32_t koff = ks * 32;
            uint32_t ah[4][4];
#pragma unroll
            for (int mt = 0; mt < 4; mt++)
                LDSM_X4(ah[mt][0], ah[mt][1], ah[mt][2], ah[mt][3],
                        aB + a_off + mt * (16 * GPAD * 2) + koff);
#pragma unroll
            for (int ntp = 0; ntp < 2; ntp++) {
                const uint32_t boff = b4_base + ntp * (16 * GPAD * 2) + koff;
                uint32_t b0, b1, b2, b3;
                LDSM_X4(b0, b1, b2, b3, wB + boff);
#pragma unroll
                for (int mt = 0; mt < 4; mt++) {
                    mma_f16(acc[mt][2 * ntp],     ah[mt][0], ah[mt][1], ah[mt][2], ah[mt][3], b0, b1);
                    mma_f16(acc[mt][2 * ntp + 1], ah[mt][0], ah[mt][1], ah[mt][2], ah[mt][3], b2, b3);
                }
            }
        }

        // load into (t+2)%3 — never the stage being read (t%3) or next (t+1)%3
        if (t + 2 < NT) {
            load_stage(t + 2);
            CP_COMMIT();
        }
    }

    // Epilogue
#pragma unroll
    for (int mt = 0; mt < 4; mt++) {
#pragma unroll
        for (int nt = 0; nt < 4; nt++) {
            int r0 = bm + moff + mt * 16 + (lane >> 2);
            int c0 = bn + noff + nt * 8 + (lane & 3) * 2;
            if (OUTMODE == 2) {
                *(float2*)(Cf + (size_t)r0 * EDIM + c0) = make_float2(acc[mt][nt][0], acc[mt][nt][1]);
                *(float2*)(Cf + (size_t)(r0 + 8) * EDIM + c0) = make_float2(acc[mt][nt][2], acc[mt][nt][3]);
            } else {
                *(uint32_t*)(Ch + (size_t)r0 * EDIM + c0) =
                    pack_h2(acc[mt][nt][0] * scale, acc[mt][nt][1] * scale);
                *(uint32_t*)(Ch + (size_t)(r0 + 8) * EDIM + c0) =
                    pack_h2(acc[mt][nt][2] * scale, acc[mt][nt][3] * scale);
            }
        }
    }
}

__global__ __launch_bounds__(256, 2) void hgemm_qkv()
{
    switch (blockIdx.z) {
        case 0: gemm_body<1>(g_qs, g_wq, nullptr, g_Q, QSCALE_LOG2); break;
        case 1: gemm_body<1>(g_ks, g_wk, nullptr, g_K, 1.0f); break;
        case 2: gemm_body<1>(g_vs, g_wv, nullptr, g_V, 1.0f); break;
    }
}

__global__ __launch_bounds__(256, 2) void hgemm_out(float* __restrict__ out)
{
    gemm_body<2>(g_Oh, g_wo, out, nullptr, 1.0f);
}

// ---------------------------------------------------------------------------
// Flash attention, fp16, log2-domain softmax. 4-stage cp.async KV ring.
// CTA 128 q-rows; 8 warps x 16 rows; 64-row KV stages; 2 CTAs/SM.
// ---------------------------------------------------------------------------
#define FPAD 72
#define FQ_BYTES (128 * FPAD * 2)        // 18432
#define FKV_BYTES (64 * FPAD * 2)        // 9216
#define FSTAGE (2 * FKV_BYTES)           // 18432 (K, V)
#define FSMEM_BYTES (FQ_BYTES + 4 * FSTAGE)   // 92160 -> 2 CTAs/SM

__global__ __launch_bounds__(256, 2) void flash_hmma()
{
    extern __shared__ __half fsm[];
    const uint32_t sb = smem_u32(fsm);
    const uint32_t qB = sb;
    const uint32_t kvB = sb + FQ_BYTES;

    const int tid = threadIdx.x;
    const int wid = tid >> 5;
    const int lane = tid & 31;
    const int qb = blockIdx.x * 128;
    const int h = blockIdx.y;
    const int b = blockIdx.z;

    const size_t qbase = ((size_t)b * SEQ + qb) * EDIM + h * HDIM;
    const size_t kvbase = (size_t)b * SEQ * EDIM + h * HDIM;

    // Q tile -> smem
#pragma unroll
    for (int it = 0; it < 4; it++) {
        int l = it * 256 + tid;     // 0..1023 chunks of 8 halves
        int r = l >> 3;
        int c = (l & 7) * 8;
        *(uint4*)(fsm + r * FPAD + c) = *(const uint4*)(g_Q + qbase + (size_t)r * EDIM + c);
    }

    const int lr = tid >> 3;
    const int lc = (tid & 7) * 8;
    const size_t gKV0 = kvbase + (size_t)lr * EDIM + lc;
    const uint32_t sKV0 = (uint32_t)(lr * FPAD + lc) * 2;
    const uint32_t sKV1 = (uint32_t)((lr + 32) * FPAD + lc) * 2;

    auto load_stage = [&](int t) {
        const uint32_t s0 = kvB + (t % 4) * FSTAGE;
        const size_t g0 = gKV0 + (size_t)t * 64 * EDIM;
        CP_ASYNC16(s0 + sKV0, g_K + g0);
        CP_ASYNC16(s0 + sKV1, g_K + g0 + (size_t)32 * EDIM);
        CP_ASYNC16(s0 + FKV_BYTES + sKV0, g_V + g0);
        CP_ASYNC16(s0 + FKV_BYTES + sKV1, g_V + g0 + (size_t)32 * EDIM);
    };

    load_stage(0); CP_COMMIT();
    load_stage(1); CP_COMMIT();
    load_stage(2); CP_COMMIT();
    __syncthreads();   // publish Q

    // Hoist Q fragments
    const uint32_t a_off = ((wid * 16 + (lane & 15)) * FPAD + (lane >> 4) * 8) * 2;
    uint32_t qh[4][4];
#pragma unroll
    for (int ks = 0; ks < 4; ks++)
        LDSM_X4(qh[ks][0], qh[ks][1], qh[ks][2], qh[ks][3], qB + a_off + ks * 32);

    const uint32_t k4_off =
        ((((lane >> 4) & 1) * 8 + (lane & 7)) * FPAD + ((lane >> 3) & 1) * 8) * 2;
    const uint32_t v4_off =
        (((lane & 7) + ((lane >> 3) & 1) * 8) * FPAD + ((lane >> 4) & 1) * 8) * 2;

    float o[8][4];
#pragma unroll
    for (int nt = 0; nt < 8; nt++)
#pragma unroll
        for (int r = 0; r < 4; r++) o[nt][r] = 0.f;
    float m0 = -1e30f, m1 = -1e30f, l0 = 0.f, l1 = 0.f;

    const int NT = SEQ / 64;   // 32

    for (int t = 0; t < NT; t++) {
        // pending after stage t completes: min(2, NT-1-t)
        int rem = NT - 1 - t;
        if (rem >= 2) CP_WAIT2(); else if (rem == 1) CP_WAIT1(); else CP_WAIT0();
        __syncthreads();

        const uint32_t s0 = kvB + (t % 4) * FSTAGE;
        const uint32_t kB = s0;
        const uint32_t vB = s0 + FKV_BYTES;

        // --- S = Q K^T (log2-scaled) ---
        float s[8][4];
#pragma unroll
        for (int nt = 0; nt < 8; nt++)
#pragma unroll
            for (int r = 0; r < 4; r++) s[nt][r] = 0.f;

#pragma unroll
        for (int ks = 0; ks < 4; ks++) {
            const uint32_t koff = ks * 32;
#pragma unroll
            for (int ntp = 0; ntp < 4; ntp++) {
                const uint32_t boff = k4_off + ntp * (16 * FPAD * 2) + koff;
                uint32_t h0, h1, h2, h3;
                LDSM_X4(h0, h1, h2, h3, kB + boff);
                mma_f16(s[2 * ntp],     qh[ks][0], qh[ks][1], qh[ks][2], qh[ks][3], h0, h1);
                mma_f16(s[2 * ntp + 1], qh[ks][0], qh[ks][1], qh[ks][2], qh[ks][3], h2, h3);
            }
        }

        // --- online softmax (base 2) ---
        float mx0 = -1e30f, mx1 = -1e30f;
#pragma unroll
        for (int nt = 0; nt < 8; nt++) {
            mx0 = fmaxf(mx0, fmaxf(s[nt][0], s[nt][1]));
            mx1 = fmaxf(mx1, fmaxf(s[nt][2], s[nt][3]));
        }
        mx0 = fmaxf(mx0, __shfl_xor_sync(0xffffffffu, mx0, 1));
        mx0 = fmaxf(mx0, __shfl_xor_sync(0xffffffffu, mx0, 2));
        mx1 = fmaxf(mx1, __shfl_xor_sync(0xffffffffu, mx1, 1));
        mx1 = fmaxf(mx1, __shfl_xor_sync(0xffffffffu, mx1, 2));

        float mn0 = fmaxf(m0, mx0), mn1 = fmaxf(m1, mx1);
        float al0 = exp2f(m0 - mn0), al1 = exp2f(m1 - mn1);
        m0 = mn0; m1 = mn1;

        float sum0 = 0.f, sum1 = 0.f;
#pragma unroll
        for (int nt = 0; nt < 8; nt++) {
            s[nt][0] = exp2f(s[nt][0] - mn0);
            s[nt][1] = exp2f(s[nt][1] - mn0);
            s[nt][2] = exp2f(s[nt][2] - mn1);
            s[nt][3] = exp2f(s[nt][3] - mn1);
            sum0 += s[nt][0] + s[nt][1];
            sum1 += s[nt][2] + s[nt][3];
        }
        sum0 += __shfl_xor_sync(0xffffffffu, sum0, 1);
        sum0 += __shfl_xor_sync(0xffffffffu, sum0, 2);
        sum1 += __shfl_xor_sync(0xffffffffu, sum1, 1);
        sum1 += __shfl_xor_sync(0xffffffffu, sum1, 2);
        l0 = l0 * al0 + sum0;
        l1 = l1 * al1 + sum1;

#pragma unroll
        for (int nt = 0; nt < 8; nt++) {
            o[nt][0] *= al0; o[nt][1] *= al0;
            o[nt][2] *= al1; o[nt][3] *= al1;
        }

        // --- O += P V ---
#pragma unroll
        for (int kt = 0; kt < 4; kt++) {
            uint32_t ph[4];
            ph[0] = pack_h2(s[2 * kt][0],     s[2 * kt][1]);
            ph[1] = pack_h2(s[2 * kt][2],     s[2 * kt][3]);
            ph[2] = pack_h2(s[2 * kt + 1][0], s[2 * kt + 1][1]);
            ph[3] = pack_h2(s[2 * kt + 1][2], s[2 * kt + 1][3]);
#pragma unroll
            for (int ntp = 0; ntp < 4; ntp++) {
                const uint32_t voff = v4_off + kt * (16 * FPAD * 2) + ntp * 32;
                uint32_t vh0, vh1, vh2, vh3;
                LDSM_X4T(vh0, vh1, vh2, vh3, vB + voff);
                mma_f16(o[2 * ntp],     ph[0], ph[1], ph[2], ph[3], vh0, vh1);
                mma_f16(o[2 * ntp + 1], ph[0], ph[1], ph[2], ph[3], vh2, vh3);
            }
        }

        // load into (t+3)%4 — distinct from stages t, t+1, t+2 in use
        if (t + 3 < NT) {
            load_stage(t + 3);
            CP_COMMIT();
        }
    }

    // Epilogue: normalize, store fp16
    const int r0 = qb + wid * 16 + (lane >> 2);
    float inv0 = 1.f / l0, inv1 = 1.f / l1;
    const size_t obase = ((size_t)b * SEQ + r0) * EDIM + h * HDIM;
#pragma unroll
    for (int nt = 0; nt < 8; nt++) {
        int c = nt * 8 + (lane & 3) * 2;
        *(uint32_t*)(g_Oh + obase + c) = pack_h2(o[nt][0] * inv0, o[nt][1] * inv0);
        *(uint32_t*)(g_Oh + obase + (size_t)8 * EDIM + c) = pack_h2(o[nt][2] * inv1, o[nt][3] * inv1);
    }
}

// ---------------------------------------------------------------------------
// Launch: 4 kernels total
// ---------------------------------------------------------------------------
extern "C" void kernel_launch(void* const* d_in, const int* in_sizes, int n_in,
                              void* d_out, int out_size)
{
    (void)in_sizes; (void)n_in; (void)out_size;
    const float* q  = (const float*)d_in[0];
    const float* k  = (const float*)d_in[1];
    const float* v  = (const float*)d_in[2];
    const float* Wq = (const float*)d_in[3];
    const float* Wk = (const float*)d_in[4];
    const float* Wv = (const float*)d_in[5];
    const float* Wo = (const float*)d_in[6];
    float* out = (float*)d_out;

    static int attr_set = 0;
    if (!attr_set) {
        cudaFuncSetAttribute(hgemm_qkv,
                             cudaFuncAttributeMaxDynamicSharedMemorySize, GSMEM_BYTES);
        cudaFuncSetAttribute(hgemm_out,
                             cudaFuncAttributeMaxDynamicSharedMemorySize, GSMEM_BYTES);
        cudaFuncSetAttribute(flash_hmma,
                             cudaFuncAttributeMaxDynamicSharedMemorySize, FSMEM_BYTES);
        attr_set = 1;
    }

    const int nA = MROWS * EDIM;

    // 1) Convert all inputs to fp16
    dim3 sgrid(nA / 1024, 7);
    cvt_all_kernel<<<sgrid, 256>>>(q, k, v, Wq, Wk, Wv, Wo);

    // 2) Merged QKV projections (Q pre-scaled into log2 domain)
    dim3 qkvgrid(EDIM / 128, MROWS / 128, 3);
    hgemm_qkv<<<qkvgrid, 256, GSMEM_BYTES>>>();

    // 3) Flash attention
    dim3 fgrid(SEQ / 128, NHEADS, BATCH);
    flash_hmma<<<fgrid, 256, FSMEM_BYTES>>>();

    // 4) Output projection
    dim3 ogrid(EDIM / 128, MROWS / 128);
    hgemm_out<<<ogrid, 256, GSMEM_BYTES>>>(out);
}